// round 6
// baseline (speedup 1.0000x reference)
#include <cuda_runtime.h>
#include <math.h>
#include <stdint.h>

#define NB    2
#define NL    1024
#define NV    8
#define NDVP  128
#define NDQ   1024
#define NDSRC 512
#define NW    4
#define NK    8
#define NROWS (NB * NV * NL)

// ---------------------------------------------------------------------------
// Scratch. A-layout: [K rows][m-perm, hi/lo interleaved], row len 2*M.
//          B-layout: [N rows][k-perm, hi/lo interleaved], row len 2*K.
// ---------------------------------------------------------------------------
__device__ float g_q [1024 * 4096];    // query  A-layout [k=1024][2*2048]
__device__ float g_k [1024 * 4096];    // key_t  A-layout
__device__ float g_wq[1024 * 2048];    // wq     B-layout [n=1024][2*1024]
__device__ float g_wk[1024 * 2048];    // wk     B-layout
__device__ float g_pq[8 * 128 * 4096]; // proj-q A-layout per v [128][2*2048]
__device__ float g_pk[8 * 2048 * 256]; // proj-k B-layout per v [2048][2*128]
__device__ float g_score[16 * 1024 * 1024];
__device__ float g_wt[NROWS * NK];
__device__ int   g_ix[NROWS * NK];

// ---------------------------------------------------------------------------
// helpers
// ---------------------------------------------------------------------------
__device__ __forceinline__ float tf32_round(float x) {
    uint32_t u;
    asm("cvt.rna.tf32.f32 %0, %1;" : "=r"(u) : "f"(x));
    return __uint_as_float(u);
}
__device__ __forceinline__ uint32_t smem_u32(const void* p) {
    uint32_t a;
    asm("{ .reg .u64 t; cvta.to.shared.u64 t, %1; cvt.u32.u64 %0, t; }" : "=r"(a) : "l"(p));
    return a;
}
__device__ __forceinline__ void cp16(uint32_t dst, const void* src) {
    asm volatile("cp.async.cg.shared.global [%0], [%1], 16;" :: "r"(dst), "l"(src) : "memory");
}
__device__ __forceinline__ void cp_commit() { asm volatile("cp.async.commit_group;" ::: "memory"); }
__device__ __forceinline__ void cp_wait2()  { asm volatile("cp.async.wait_group 2;" ::: "memory"); }
__device__ __forceinline__ void cp_wait0()  { asm volatile("cp.async.wait_group 0;" ::: "memory"); }

__device__ __forceinline__ void mma_tf32(float* d, const uint32_t* a, const uint32_t* b) {
    asm volatile(
        "mma.sync.aligned.m16n8k8.row.col.f32.tf32.tf32.f32 "
        "{%0,%1,%2,%3}, {%4,%5,%6,%7}, {%8,%9}, {%0,%1,%2,%3};"
        : "+f"(d[0]), "+f"(d[1]), "+f"(d[2]), "+f"(d[3])
        : "r"(a[0]), "r"(a[1]), "r"(a[2]), "r"(a[3]), "r"(b[0]), "r"(b[1]));
}

// float index of hi(m) within an A-layout row (lo = +1)
__host__ __device__ __forceinline__ int Afpos(int m) {
    return ((m >> 4) << 5) + 2 * (2 * (m & 7) + ((m >> 3) & 1));
}
// float index of hi(k) within a B-layout row (lo = +1)
__host__ __device__ __forceinline__ int Bfpos(int k) {
    return ((k >> 3) << 4) + ((k & 3) << 2) + (((k >> 2) & 1) << 1);
}

// ---------------------------------------------------------------------------
// GEMM: BM=128, BN=128, BK=16, 128 threads (4 warps 2x2, 64x64 warp tile),
// 3-stage cp.async pipeline.
// Smem per stage: A [16][256] floats, B [128][40] floats (pad 8).
// ---------------------------------------------------------------------------
#define SB_OFF    4096                 // floats: B tile after A tile
#define STAGE_F   (4096 + 128 * 40)    // 9216 floats
#define NSTAGE    3
#define SMEM_BYTES (NSTAGE * STAGE_F * 4)  // 110592

__device__ __forceinline__ void load_stage(uint32_t sb,
    const float* Ap, int lda, const float* Bp, int ldb, int t)
{
    #pragma unroll
    for (int i = 0; i < 8; i++) {
        const int id = threadIdx.x + i * 128;   // 1024 A chunks
        cp16(sb + (uint32_t)(((id >> 6) << 8) + (id & 63) * 4) * 4,
             Ap + (size_t)(16 * t + (id >> 6)) * lda + (id & 63) * 4);
    }
    #pragma unroll
    for (int i = 0; i < 8; i++) {
        const int id = threadIdx.x + i * 128;   // 1024 B chunks
        cp16(sb + (uint32_t)(SB_OFF + (id >> 3) * 40 + (id & 7) * 4) * 4,
             Bp + (size_t)(id >> 3) * ldb + 32 * t + (id & 7) * 4);
    }
    cp_commit();
}

__device__ __forceinline__ void compute_stage(const float* sA, const float* sB,
                                              int warp_m, int warp_n, float acc[4][8][4])
{
    const int lane = threadIdx.x & 31;
    const int g = lane >> 2, tg = lane & 3;
    #pragma unroll
    for (int h = 0; h < 2; h++) {
        float4 af0[4], af1[4];
        #pragma unroll
        for (int ma = 0; ma < 4; ma++) {
            const int co = (warp_m + ma * 16) * 2 + 4 * g;
            af0[ma] = *(const float4*)&sA[(h * 8 + tg) * 256 + co];
            af1[ma] = *(const float4*)&sA[(h * 8 + tg + 4) * 256 + co];
        }
        #pragma unroll
        for (int nbh = 0; nbh < 2; nbh++) {
            float4 bf[4];
            #pragma unroll
            for (int j = 0; j < 4; j++) {
                const int n = warp_n + (nbh * 4 + j) * 8 + g;
                bf[j] = *(const float4*)&sB[n * 40 + h * 16 + 4 * tg];
            }
            #pragma unroll
            for (int ma = 0; ma < 4; ma++) {
                uint32_t aH[4] = {__float_as_uint(af0[ma].x), __float_as_uint(af0[ma].z),
                                  __float_as_uint(af1[ma].x), __float_as_uint(af1[ma].z)};
                uint32_t aL[4] = {__float_as_uint(af0[ma].y), __float_as_uint(af0[ma].w),
                                  __float_as_uint(af1[ma].y), __float_as_uint(af1[ma].w)};
                #pragma unroll
                for (int j = 0; j < 4; j++) {
                    uint32_t bH[2] = {__float_as_uint(bf[j].x), __float_as_uint(bf[j].z)};
                    uint32_t bL[2] = {__float_as_uint(bf[j].y), __float_as_uint(bf[j].w)};
                    float* d = acc[ma][nbh * 4 + j];
                    mma_tf32(d, aH, bH);
                    mma_tf32(d, aH, bL);
                    mma_tf32(d, aL, bH);
                }
            }
        }
    }
}

__device__ __forceinline__ void gemm_mainloop(
    const float* Ap, int lda, const float* Bp, int ldb,
    int nstages, float acc[4][8][4], float* smem)
{
    const uint32_t sb = smem_u32(smem);
    const int warp = threadIdx.x >> 5;
    const int warp_m = (warp & 1) * 64, warp_n = (warp >> 1) * 64;

    #pragma unroll
    for (int sp = 0; sp < NSTAGE; sp++)
        if (sp < nstages)
            load_stage(sb + sp * STAGE_F * 4, Ap, lda, Bp, ldb, sp);

    int buf = 0;
    for (int t = 0; t < nstages; ++t) {
        if (t + NSTAGE - 1 < nstages) cp_wait2(); else cp_wait0();
        __syncthreads();
        compute_stage(smem + buf * STAGE_F, smem + buf * STAGE_F + SB_OFF, warp_m, warp_n, acc);
        __syncthreads();
        if (t + NSTAGE < nstages)
            load_stage(sb + buf * STAGE_F * 4, Ap, lda, Bp, ldb, t + NSTAGE);
        buf = (buf == NSTAGE - 1) ? 0 : buf + 1;
    }
}

// ---------------------------------------------------------------------------
// Kernel 1a: split+transpose query/key -> A-layout [d][2*2048]
// ---------------------------------------------------------------------------
__global__ void __launch_bounds__(256) split_qk_kernel(
    const float* __restrict__ X, float* __restrict__ G)
{
    __shared__ float sh[32][33], sl[32][33];
    const int tx = threadIdx.x, ty = threadIdx.y;
    const int c0 = blockIdx.x * 32, r0 = blockIdx.y * 32;   // c: d index, r: m index
    #pragma unroll
    for (int j = 0; j < 4; j++) {
        const int r = r0 + ty + j * 8;
        const float v = X[(size_t)r * 1024 + c0 + tx];
        const float h = tf32_round(v);
        sh[ty + j * 8][tx] = h;
        sl[ty + j * 8][tx] = tf32_round(v - h);
    }
    __syncthreads();
    #pragma unroll
    for (int j = 0; j < 4; j++) {
        const int c = c0 + ty + j * 8;
        *(float2*)&G[(size_t)c * 4096 + Afpos(r0 + tx)] =
            make_float2(sh[tx][ty + j * 8], sl[tx][ty + j * 8]);
    }
}

// ---------------------------------------------------------------------------
// Kernel 1b: split wq/wk -> B-layout [n][2*1024]
// ---------------------------------------------------------------------------
__global__ void __launch_bounds__(256) split_w_kernel(
    const float* __restrict__ W, float* __restrict__ G)
{
    const int id = blockIdx.x * 256 + threadIdx.x;
    const int n = id >> 10, k = id & 1023;
    const float v = W[id];
    const float h = tf32_round(v);
    *(float2*)&G[(size_t)n * 2048 + Bfpos(k)] = make_float2(h, tf32_round(v - h));
}

// ---------------------------------------------------------------------------
// Kernel 2: projections. z=0 -> q, z=1 -> k. grid (8, 16, 2), 128 thr.
// Epilogue: +bias, split, store to score-GEMM layouts.
// ---------------------------------------------------------------------------
__global__ void __launch_bounds__(128, 1) proj_mma_kernel(
    const float* __restrict__ bq, const float* __restrict__ bk)
{
    extern __shared__ float smem[];
    const int z = blockIdx.z;
    const int m0 = blockIdx.y * 128, n0 = blockIdx.x * 128;

    const float* Ap = (z ? g_k : g_q) + 2 * m0;               // lda 4096
    const float* Bp = (z ? g_wk : g_wq) + (size_t)n0 * 2048;  // ldb 2048

    float acc[4][8][4];
    #pragma unroll
    for (int i = 0; i < 4; i++)
        #pragma unroll
        for (int j = 0; j < 8; j++)
            #pragma unroll
            for (int r = 0; r < 4; r++) acc[i][j][r] = 0.f;

    gemm_mainloop(Ap, 4096, Bp, 2048, NDQ / 16, acc, smem);

    const float* bias = z ? bk : bq;
    const int warp = threadIdx.x >> 5, lane = threadIdx.x & 31;
    const int warp_m = (warp & 1) * 64, warp_n = (warp >> 1) * 64;
    const int g = lane >> 2, tg = lane & 3;

    #pragma unroll
    for (int ma = 0; ma < 4; ma++)
        #pragma unroll
        for (int nb = 0; nb < 8; nb++) {
            const int row = m0 + warp_m + ma * 16 + g;
            const int col = n0 + warp_n + nb * 8 + 2 * tg;
            #pragma unroll
            for (int rr = 0; rr < 4; rr++) {
                const int r = row + (rr >> 1) * 8;
                const int c = col + (rr & 1);
                const float v = acc[ma][nb][rr] + __ldg(&bias[c]);
                const float h = tf32_round(v);
                const float l = tf32_round(v - h);
                const int vi = c >> 7, kk = c & 127;
                if (z == 0)
                    *(float2*)&g_pq[((size_t)(vi * 128 + kk)) * 4096 + Afpos(r)] =
                        make_float2(h, l);
                else
                    *(float2*)&g_pk[((size_t)(vi * 2048 + r)) * 256 + Bfpos(kk)] =
                        make_float2(h, l);
            }
        }
}

// ---------------------------------------------------------------------------
// Kernel 3: score[b,v] = q_v * k_v^T (K=128). grid (8, 8, 16), 128 thr.
// ---------------------------------------------------------------------------
__global__ void __launch_bounds__(128, 1) score_mma_kernel()
{
    extern __shared__ float smem[];
    const int z = blockIdx.z;
    const int b = z >> 3, v = z & 7;
    const int m0 = blockIdx.y * 128, n0 = blockIdx.x * 128;

    const float* Ap = g_pq + (size_t)v * 128 * 4096 + 2 * (b * 1024 + m0);   // lda 4096
    const float* Bp = g_pk + ((size_t)v * 2048 + b * 1024 + n0) * 256;       // ldb 256

    float acc[4][8][4];
    #pragma unroll
    for (int i = 0; i < 4; i++)
        #pragma unroll
        for (int j = 0; j < 8; j++)
            #pragma unroll
            for (int r = 0; r < 4; r++) acc[i][j][r] = 0.f;

    gemm_mainloop(Ap, 4096, Bp, 256, NDVP / 16, acc, smem);

    float* C = g_score + ((size_t)z << 20);
    const int warp = threadIdx.x >> 5, lane = threadIdx.x & 31;
    const int warp_m = (warp & 1) * 64, warp_n = (warp >> 1) * 64;
    const int g = lane >> 2, tg = lane & 3;

    #pragma unroll
    for (int ma = 0; ma < 4; ma++)
        #pragma unroll
        for (int nb = 0; nb < 8; nb++) {
            const int row = m0 + warp_m + ma * 16 + g;
            const int col = n0 + warp_n + nb * 8 + 2 * tg;
            *(float2*)&C[(size_t)row * 1024 + col] =
                make_float2(acc[ma][nb][0], acc[ma][nb][1]);
            *(float2*)&C[(size_t)(row + 8) * 1024 + col] =
                make_float2(acc[ma][nb][2], acc[ma][nb][3]);
        }
}

// ---------------------------------------------------------------------------
// Kernel 4: top-8 + softmax per score row. One warp per row.
// ---------------------------------------------------------------------------
__global__ void __launch_bounds__(256) topk_kernel()
{
    const int rid  = blockIdx.x * 8 + (threadIdx.x >> 5);
    const int lane = threadIdx.x & 31;
    const float* row = g_score + (size_t)rid * NL;

    float best[NK];
    int   bidx[NK];
    #pragma unroll
    for (int j = 0; j < NK; j++) { best[j] = -INFINITY; bidx[j] = 0x7fffffff; }

    #pragma unroll 4
    for (int i = 0; i < 32; i++) {
        const int idx = i * 32 + lane;
        const float val = row[idx];
        if (val > best[NK - 1]) {
            best[NK - 1] = val; bidx[NK - 1] = idx;
            #pragma unroll
            for (int j = NK - 1; j > 0; --j) {
                if (best[j] > best[j - 1]) {
                    float tv = best[j]; best[j] = best[j - 1]; best[j - 1] = tv;
                    int   ti = bidx[j]; bidx[j] = bidx[j - 1]; bidx[j - 1] = ti;
                }
            }
        }
    }

    float vals[NK]; int inds[NK];
    #pragma unroll
    for (int r = 0; r < NK; r++) {
        float v0 = best[0]; int i0 = bidx[0];
        #pragma unroll
        for (int off = 16; off > 0; off >>= 1) {
            float ov = __shfl_down_sync(0xffffffffu, v0, off);
            int   oi = __shfl_down_sync(0xffffffffu, i0, off);
            if (ov > v0 || (ov == v0 && oi < i0)) { v0 = ov; i0 = oi; }
        }
        v0 = __shfl_sync(0xffffffffu, v0, 0);
        i0 = __shfl_sync(0xffffffffu, i0, 0);
        vals[r] = v0; inds[r] = i0;
        if (lane == (i0 & 31)) {
            #pragma unroll
            for (int j = 0; j < NK - 1; j++) { best[j] = best[j + 1]; bidx[j] = bidx[j + 1]; }
            best[NK - 1] = -INFINITY; bidx[NK - 1] = 0x7fffffff;
        }
    }

    if (lane == 0) {
        const float m = vals[0];
        float e[NK], sum = 0.f;
        #pragma unroll
        for (int r = 0; r < NK; r++) { e[r] = expf(vals[r] - m); sum += e[r]; }
        const float inv = 1.f / sum;
        #pragma unroll
        for (int r = 0; r < NK; r++) {
            g_wt[rid * NK + r] = e[r] * inv;
            g_ix[rid * NK + r] = inds[r];
        }
    }
}

// ---------------------------------------------------------------------------
// Kernel 5: windowed gather + weighted sum. grid (1024, 8, 2), 256 threads.
// ---------------------------------------------------------------------------
__global__ void __launch_bounds__(256) out_kernel(
    const float* __restrict__ source, float* __restrict__ out)
{
    const int q = blockIdx.x, v = blockIdx.y, b = blockIdx.z;
    const int tid = threadIdx.x;
    const int rid = (b * NV + v) * NL + q;

    float wloc[NK]; int iloc[NK];
    #pragma unroll
    for (int r = 0; r < NK; r++) {
        wloc[r] = __ldg(&g_wt[rid * NK + r]);
        iloc[r] = __ldg(&g_ix[rid * NK + r]);
    }

    const float4* src4 = (const float4*)(source + b * (NL * NDSRC));
    float4* out4 = (float4*)out + (size_t)rid * (NW * NDSRC / 4);

    #pragma unroll
    for (int e2 = 0; e2 < 2; e2++) {
        const int id = tid + e2 * 256;
        const int w = id >> 7;
        const int f = id & 127;
        float4 acc = make_float4(0.f, 0.f, 0.f, 0.f);
        #pragma unroll
        for (int r = 0; r < NK; r++) {
            const int rr = iloc[r] + w - 1;
            if ((unsigned)rr < (unsigned)NL) {
                const float4 s = __ldg(&src4[rr * (NDSRC / 4) + f]);
                const float wt = wloc[r];
                acc.x += wt * s.x; acc.y += wt * s.y;
                acc.z += wt * s.z; acc.w += wt * s.w;
            }
        }
        out4[id] = acc;
    }
}

// ---------------------------------------------------------------------------
extern "C" void kernel_launch(void* const* d_in, const int* in_sizes, int n_in,
                              void* d_out, int out_size)
{
    const float* query  = (const float*)d_in[0];
    const float* key_t  = (const float*)d_in[1];
    const float* source = (const float*)d_in[2];
    const float* wq     = (const float*)d_in[3];
    const float* bq     = (const float*)d_in[4];
    const float* wk     = (const float*)d_in[5];
    const float* bk     = (const float*)d_in[6];
    float* out = (float*)d_out;

    static int inited = 0;
    if (!inited) {
        cudaFuncSetAttribute(proj_mma_kernel,  cudaFuncAttributeMaxDynamicSharedMemorySize, SMEM_BYTES);
        cudaFuncSetAttribute(score_mma_kernel, cudaFuncAttributeMaxDynamicSharedMemorySize, SMEM_BYTES);
        inited = 1;
    }

    void *p_q, *p_k, *p_wq, *p_wk;
    cudaGetSymbolAddress(&p_q,  g_q);  cudaGetSymbolAddress(&p_k,  g_k);
    cudaGetSymbolAddress(&p_wq, g_wq); cudaGetSymbolAddress(&p_wk, g_wk);

    // 1) split inputs into permuted hi/lo layouts
    split_qk_kernel<<<dim3(32, 64), dim3(32, 8)>>>(query, (float*)p_q);
    split_qk_kernel<<<dim3(32, 64), dim3(32, 8)>>>(key_t, (float*)p_k);
    split_w_kernel<<<4096, 256>>>(wq, (float*)p_wq);
    split_w_kernel<<<4096, 256>>>(wk, (float*)p_wk);

    // 2) projections
    proj_mma_kernel<<<dim3(8, 16, 2), 128, SMEM_BYTES>>>(bq, bk);

    // 3) score GEMMs
    score_mma_kernel<<<dim3(8, 8, 16), 128, SMEM_BYTES>>>();

    // 4) top-8 + softmax
    topk_kernel<<<NROWS / 8, 256>>>();

    // 5) gather + weighted sum
    out_kernel<<<dim3(NL, NV, NB), 256>>>(source, out);
}

// round 7
// speedup vs baseline: 1.0737x; 1.0737x over previous
#include <cuda_runtime.h>
#include <math.h>
#include <stdint.h>

#define NB    2
#define NL    1024
#define NV    8
#define NDVP  128
#define NDQ   1024
#define NDSRC 512
#define NW    4
#define NK    8
#define NROWS (NB * NV * NL)

// ---------------------------------------------------------------------------
// Scratch. A-layout: [K rows][m-perm, hi/lo interleaved], row len 2*M.
//          B-layout: [N rows][k-perm, hi/lo interleaved], row len 2*K.
// ---------------------------------------------------------------------------
__device__ float g_q [1024 * 4096];    // query  A-layout [k=1024][2*2048]
__device__ float g_k [1024 * 4096];    // key_t  A-layout
__device__ float g_wq[1024 * 2048];    // wq     B-layout [n=1024][2*1024]
__device__ float g_wk[1024 * 2048];    // wk     B-layout
__device__ float g_pq[8 * 128 * 4096]; // proj-q A-layout per v [128][2*2048]
__device__ float g_pk[8 * 2048 * 256]; // proj-k B-layout per v [2048][2*128]
__device__ float g_score[16 * 1024 * 1024];
__device__ float g_wt[NROWS * NK];
__device__ int   g_ix[NROWS * NK];

// ---------------------------------------------------------------------------
// helpers
// ---------------------------------------------------------------------------
__device__ __forceinline__ float tf32_round(float x) {
    uint32_t u;
    asm("cvt.rna.tf32.f32 %0, %1;" : "=r"(u) : "f"(x));
    return __uint_as_float(u);
}
__device__ __forceinline__ uint32_t smem_u32(const void* p) {
    uint32_t a;
    asm("{ .reg .u64 t; cvta.to.shared.u64 t, %1; cvt.u32.u64 %0, t; }" : "=r"(a) : "l"(p));
    return a;
}
__device__ __forceinline__ void cp16(uint32_t dst, const void* src) {
    asm volatile("cp.async.cg.shared.global [%0], [%1], 16;" :: "r"(dst), "l"(src) : "memory");
}
__device__ __forceinline__ void cp_commit() { asm volatile("cp.async.commit_group;" ::: "memory"); }
__device__ __forceinline__ void cp_wait2()  { asm volatile("cp.async.wait_group 2;" ::: "memory"); }
__device__ __forceinline__ void cp_wait0()  { asm volatile("cp.async.wait_group 0;" ::: "memory"); }

__device__ __forceinline__ void mma_tf32(float* d, const uint32_t* a, const uint32_t* b) {
    asm volatile(
        "mma.sync.aligned.m16n8k8.row.col.f32.tf32.tf32.f32 "
        "{%0,%1,%2,%3}, {%4,%5,%6,%7}, {%8,%9}, {%0,%1,%2,%3};"
        : "+f"(d[0]), "+f"(d[1]), "+f"(d[2]), "+f"(d[3])
        : "r"(a[0]), "r"(a[1]), "r"(a[2]), "r"(a[3]), "r"(b[0]), "r"(b[1]));
}

// float index of hi(m) within an A-layout row (lo = +1)
__host__ __device__ __forceinline__ int Afpos(int m) {
    return ((m >> 4) << 5) + 2 * (2 * (m & 7) + ((m >> 3) & 1));
}
// float index of hi(k) within a B-layout row (lo = +1)
__host__ __device__ __forceinline__ int Bfpos(int k) {
    return ((k >> 3) << 4) + ((k & 3) << 2) + (((k >> 2) & 1) << 1);
}
// smem B chunk swizzle (16B chunks within a 8-chunk row)
__device__ __forceinline__ int swz(int n) {
    return ((n & 1) << 2) | ((n >> 1) & 3);
}

// ---------------------------------------------------------------------------
// GEMM: BM=128, BN=128, BK=16, 128 threads (4 warps 2x2, 64x64 warp tile),
// 3-stage cp.async pipeline.
// Smem per stage: A [16][264] floats (stride 264 = 8 mod 32 banks, conflict
// free), B [128][32] floats with XOR chunk swizzle (conflict free, no pad).
// ---------------------------------------------------------------------------
#define SA_ST     264
#define SB_OFF    (16 * SA_ST)           // 4224 floats
#define STAGE_F   (SB_OFF + 128 * 32)    // 8320 floats
#define NSTAGE    3
#define SMEM_BYTES (NSTAGE * STAGE_F * 4)  // 99840

__device__ __forceinline__ void load_stage(uint32_t sb,
    const float* Ap, int lda, const float* Bp, int ldb, int t)
{
    #pragma unroll
    for (int i = 0; i < 8; i++) {
        const int id = threadIdx.x + i * 128;   // 1024 A chunks (16 rows x 64)
        cp16(sb + (uint32_t)((id >> 6) * SA_ST + (id & 63) * 4) * 4,
             Ap + (size_t)(16 * t + (id >> 6)) * lda + (id & 63) * 4);
    }
    #pragma unroll
    for (int i = 0; i < 8; i++) {
        const int id = threadIdx.x + i * 128;   // 1024 B chunks (128 rows x 8)
        const int n = id >> 3, c = id & 7;
        cp16(sb + (uint32_t)(SB_OFF + n * 32 + ((c ^ swz(n)) << 2)) * 4,
             Bp + (size_t)n * ldb + 32 * t + c * 4);
    }
    cp_commit();
}

__device__ __forceinline__ void compute_stage(const float* sA, const float* sB,
                                              int warp_m, int warp_n, float acc[4][8][4])
{
    const int lane = threadIdx.x & 31;
    const int g = lane >> 2, tg = lane & 3;
    #pragma unroll
    for (int h = 0; h < 2; h++) {
        float4 af0[4], af1[4];
        #pragma unroll
        for (int ma = 0; ma < 4; ma++) {
            const int co = (warp_m + ma * 16) * 2 + 4 * g;
            af0[ma] = *(const float4*)&sA[(h * 8 + tg) * SA_ST + co];
            af1[ma] = *(const float4*)&sA[(h * 8 + tg + 4) * SA_ST + co];
        }
        #pragma unroll
        for (int nbh = 0; nbh < 2; nbh++) {
            float4 bf[4];
            #pragma unroll
            for (int j = 0; j < 4; j++) {
                const int n = warp_n + (nbh * 4 + j) * 8 + g;
                bf[j] = *(const float4*)&sB[n * 32 + (((h * 4 + tg) ^ swz(n)) << 2)];
            }
            #pragma unroll
            for (int ma = 0; ma < 4; ma++) {
                uint32_t aH[4] = {__float_as_uint(af0[ma].x), __float_as_uint(af0[ma].z),
                                  __float_as_uint(af1[ma].x), __float_as_uint(af1[ma].z)};
                uint32_t aL[4] = {__float_as_uint(af0[ma].y), __float_as_uint(af0[ma].w),
                                  __float_as_uint(af1[ma].y), __float_as_uint(af1[ma].w)};
                #pragma unroll
                for (int j = 0; j < 4; j++) {
                    uint32_t bH[2] = {__float_as_uint(bf[j].x), __float_as_uint(bf[j].z)};
                    uint32_t bL[2] = {__float_as_uint(bf[j].y), __float_as_uint(bf[j].w)};
                    float* d = acc[ma][nbh * 4 + j];
                    mma_tf32(d, aH, bH);
                    mma_tf32(d, aH, bL);
                    mma_tf32(d, aL, bH);
                }
            }
        }
    }
}

__device__ __forceinline__ void gemm_mainloop(
    const float* Ap, int lda, const float* Bp, int ldb,
    int nstages, float acc[4][8][4], float* smem)
{
    const uint32_t sb = smem_u32(smem);
    const int warp = threadIdx.x >> 5;
    const int warp_m = (warp & 1) * 64, warp_n = (warp >> 1) * 64;

    #pragma unroll
    for (int sp = 0; sp < NSTAGE; sp++)
        if (sp < nstages)
            load_stage(sb + sp * STAGE_F * 4, Ap, lda, Bp, ldb, sp);

    int buf = 0;
    for (int t = 0; t < nstages; ++t) {
        if (t + NSTAGE - 1 < nstages) cp_wait2(); else cp_wait0();
        __syncthreads();
        compute_stage(smem + buf * STAGE_F, smem + buf * STAGE_F + SB_OFF, warp_m, warp_n, acc);
        __syncthreads();
        if (t + NSTAGE < nstages)
            load_stage(sb + buf * STAGE_F * 4, Ap, lda, Bp, ldb, t + NSTAGE);
        buf = (buf == NSTAGE - 1) ? 0 : buf + 1;
    }
}

// ---------------------------------------------------------------------------
// Kernel 1a: split+transpose query/key -> A-layout [d][2*2048]
// ---------------------------------------------------------------------------
__global__ void __launch_bounds__(256) split_qk_kernel(
    const float* __restrict__ X, float* __restrict__ G)
{
    __shared__ float sh[32][33], sl[32][33];
    const int tx = threadIdx.x, ty = threadIdx.y;
    const int c0 = blockIdx.x * 32, r0 = blockIdx.y * 32;   // c: d index, r: m index
    #pragma unroll
    for (int j = 0; j < 4; j++) {
        const int r = r0 + ty + j * 8;
        const float v = X[(size_t)r * 1024 + c0 + tx];
        const float h = tf32_round(v);
        sh[ty + j * 8][tx] = h;
        sl[ty + j * 8][tx] = tf32_round(v - h);
    }
    __syncthreads();
    #pragma unroll
    for (int j = 0; j < 4; j++) {
        const int c = c0 + ty + j * 8;
        *(float2*)&G[(size_t)c * 4096 + Afpos(r0 + tx)] =
            make_float2(sh[tx][ty + j * 8], sl[tx][ty + j * 8]);
    }
}

// ---------------------------------------------------------------------------
// Kernel 1b: split wq/wk -> B-layout [n][2*1024]
// ---------------------------------------------------------------------------
__global__ void __launch_bounds__(256) split_w_kernel(
    const float* __restrict__ W, float* __restrict__ G)
{
    const int id = blockIdx.x * 256 + threadIdx.x;
    const int n = id >> 10, k = id & 1023;
    const float v = W[id];
    const float h = tf32_round(v);
    *(float2*)&G[(size_t)n * 2048 + Bfpos(k)] = make_float2(h, tf32_round(v - h));
}

// ---------------------------------------------------------------------------
// Kernel 2: projections. z=0 -> q, z=1 -> k. grid (8, 16, 2), 128 thr.
// Epilogue: +bias, split, store to score-GEMM layouts.
// ---------------------------------------------------------------------------
__global__ void __launch_bounds__(128, 1) proj_mma_kernel(
    const float* __restrict__ bq, const float* __restrict__ bk)
{
    extern __shared__ float smem[];
    const int z = blockIdx.z;
    const int m0 = blockIdx.y * 128, n0 = blockIdx.x * 128;

    const float* Ap = (z ? g_k : g_q) + 2 * m0;               // lda 4096
    const float* Bp = (z ? g_wk : g_wq) + (size_t)n0 * 2048;  // ldb 2048

    float acc[4][8][4];
    #pragma unroll
    for (int i = 0; i < 4; i++)
        #pragma unroll
        for (int j = 0; j < 8; j++)
            #pragma unroll
            for (int r = 0; r < 4; r++) acc[i][j][r] = 0.f;

    gemm_mainloop(Ap, 4096, Bp, 2048, NDQ / 16, acc, smem);

    const float* bias = z ? bk : bq;
    const int warp = threadIdx.x >> 5, lane = threadIdx.x & 31;
    const int warp_m = (warp & 1) * 64, warp_n = (warp >> 1) * 64;
    const int g = lane >> 2, tg = lane & 3;

    #pragma unroll
    for (int ma = 0; ma < 4; ma++)
        #pragma unroll
        for (int nb = 0; nb < 8; nb++) {
            const int row = m0 + warp_m + ma * 16 + g;
            const int col = n0 + warp_n + nb * 8 + 2 * tg;
            #pragma unroll
            for (int rr = 0; rr < 4; rr++) {
                const int r = row + (rr >> 1) * 8;
                const int c = col + (rr & 1);
                const float v = acc[ma][nb][rr] + __ldg(&bias[c]);
                const float h = tf32_round(v);
                const float l = tf32_round(v - h);
                const int vi = c >> 7, kk = c & 127;
                if (z == 0)
                    *(float2*)&g_pq[((size_t)(vi * 128 + kk)) * 4096 + Afpos(r)] =
                        make_float2(h, l);
                else
                    *(float2*)&g_pk[((size_t)(vi * 2048 + r)) * 256 + Bfpos(kk)] =
                        make_float2(h, l);
            }
        }
}

// ---------------------------------------------------------------------------
// Kernel 3: score[b,v] = q_v * k_v^T (K=128). grid (8, 8, 16), 128 thr.
// ---------------------------------------------------------------------------
__global__ void __launch_bounds__(128, 1) score_mma_kernel()
{
    extern __shared__ float smem[];
    const int z = blockIdx.z;
    const int b = z >> 3, v = z & 7;
    const int m0 = blockIdx.y * 128, n0 = blockIdx.x * 128;

    const float* Ap = g_pq + (size_t)v * 128 * 4096 + 2 * (b * 1024 + m0);   // lda 4096
    const float* Bp = g_pk + ((size_t)v * 2048 + b * 1024 + n0) * 256;       // ldb 256

    float acc[4][8][4];
    #pragma unroll
    for (int i = 0; i < 4; i++)
        #pragma unroll
        for (int j = 0; j < 8; j++)
            #pragma unroll
            for (int r = 0; r < 4; r++) acc[i][j][r] = 0.f;

    gemm_mainloop(Ap, 4096, Bp, 256, NDVP / 16, acc, smem);

    float* C = g_score + ((size_t)z << 20);
    const int warp = threadIdx.x >> 5, lane = threadIdx.x & 31;
    const int warp_m = (warp & 1) * 64, warp_n = (warp >> 1) * 64;
    const int g = lane >> 2, tg = lane & 3;

    #pragma unroll
    for (int ma = 0; ma < 4; ma++)
        #pragma unroll
        for (int nb = 0; nb < 8; nb++) {
            const int row = m0 + warp_m + ma * 16 + g;
            const int col = n0 + warp_n + nb * 8 + 2 * tg;
            *(float2*)&C[(size_t)row * 1024 + col] =
                make_float2(acc[ma][nb][0], acc[ma][nb][1]);
            *(float2*)&C[(size_t)(row + 8) * 1024 + col] =
                make_float2(acc[ma][nb][2], acc[ma][nb][3]);
        }
}

// ---------------------------------------------------------------------------
// Kernel 4: top-8 + softmax per score row. One warp per row.
// ---------------------------------------------------------------------------
__global__ void __launch_bounds__(256) topk_kernel()
{
    const int rid  = blockIdx.x * 8 + (threadIdx.x >> 5);
    const int lane = threadIdx.x & 31;
    const float* row = g_score + (size_t)rid * NL;

    float best[NK];
    int   bidx[NK];
    #pragma unroll
    for (int j = 0; j < NK; j++) { best[j] = -INFINITY; bidx[j] = 0x7fffffff; }

    #pragma unroll 4
    for (int i = 0; i < 32; i++) {
        const int idx = i * 32 + lane;
        const float val = row[idx];
        if (val > best[NK - 1]) {
            best[NK - 1] = val; bidx[NK - 1] = idx;
            #pragma unroll
            for (int j = NK - 1; j > 0; --j) {
                if (best[j] > best[j - 1]) {
                    float tv = best[j]; best[j] = best[j - 1]; best[j - 1] = tv;
                    int   ti = bidx[j]; bidx[j] = bidx[j - 1]; bidx[j - 1] = ti;
                }
            }
        }
    }

    float vals[NK]; int inds[NK];
    #pragma unroll
    for (int r = 0; r < NK; r++) {
        float v0 = best[0]; int i0 = bidx[0];
        #pragma unroll
        for (int off = 16; off > 0; off >>= 1) {
            float ov = __shfl_down_sync(0xffffffffu, v0, off);
            int   oi = __shfl_down_sync(0xffffffffu, i0, off);
            if (ov > v0 || (ov == v0 && oi < i0)) { v0 = ov; i0 = oi; }
        }
        v0 = __shfl_sync(0xffffffffu, v0, 0);
        i0 = __shfl_sync(0xffffffffu, i0, 0);
        vals[r] = v0; inds[r] = i0;
        if (lane == (i0 & 31)) {
            #pragma unroll
            for (int j = 0; j < NK - 1; j++) { best[j] = best[j + 1]; bidx[j] = bidx[j + 1]; }
            best[NK - 1] = -INFINITY; bidx[NK - 1] = 0x7fffffff;
        }
    }

    if (lane == 0) {
        const float m = vals[0];
        float e[NK], sum = 0.f;
        #pragma unroll
        for (int r = 0; r < NK; r++) { e[r] = expf(vals[r] - m); sum += e[r]; }
        const float inv = 1.f / sum;
        #pragma unroll
        for (int r = 0; r < NK; r++) {
            g_wt[rid * NK + r] = e[r] * inv;
            g_ix[rid * NK + r] = inds[r];
        }
    }
}

// ---------------------------------------------------------------------------
// Kernel 5: windowed gather + weighted sum. grid (1024, 8, 2), 256 threads.
// ---------------------------------------------------------------------------
__global__ void __launch_bounds__(256) out_kernel(
    const float* __restrict__ source, float* __restrict__ out)
{
    const int q = blockIdx.x, v = blockIdx.y, b = blockIdx.z;
    const int tid = threadIdx.x;
    const int rid = (b * NV + v) * NL + q;

    float wloc[NK]; int iloc[NK];
    #pragma unroll
    for (int r = 0; r < NK; r++) {
        wloc[r] = __ldg(&g_wt[rid * NK + r]);
        iloc[r] = __ldg(&g_ix[rid * NK + r]);
    }

    const float4* src4 = (const float4*)(source + b * (NL * NDSRC));
    float4* out4 = (float4*)out + (size_t)rid * (NW * NDSRC / 4);

    #pragma unroll
    for (int e2 = 0; e2 < 2; e2++) {
        const int id = tid + e2 * 256;
        const int w = id >> 7;
        const int f = id & 127;
        float4 acc = make_float4(0.f, 0.f, 0.f, 0.f);
        #pragma unroll
        for (int r = 0; r < NK; r++) {
            const int rr = iloc[r] + w - 1;
            if ((unsigned)rr < (unsigned)NL) {
                const float4 s = __ldg(&src4[rr * (NDSRC / 4) + f]);
                const float wt = wloc[r];
                acc.x += wt * s.x; acc.y += wt * s.y;
                acc.z += wt * s.z; acc.w += wt * s.w;
            }
        }
        out4[id] = acc;
    }
}

// ---------------------------------------------------------------------------
extern "C" void kernel_launch(void* const* d_in, const int* in_sizes, int n_in,
                              void* d_out, int out_size)
{
    const float* query  = (const float*)d_in[0];
    const float* key_t  = (const float*)d_in[1];
    const float* source = (const float*)d_in[2];
    const float* wq     = (const float*)d_in[3];
    const float* bq     = (const float*)d_in[4];
    const float* wk     = (const float*)d_in[5];
    const float* bk     = (const float*)d_in[6];
    float* out = (float*)d_out;

    static int inited = 0;
    if (!inited) {
        cudaFuncSetAttribute(proj_mma_kernel,  cudaFuncAttributeMaxDynamicSharedMemorySize, SMEM_BYTES);
        cudaFuncSetAttribute(score_mma_kernel, cudaFuncAttributeMaxDynamicSharedMemorySize, SMEM_BYTES);
        inited = 1;
    }

    void *p_q, *p_k, *p_wq, *p_wk;
    cudaGetSymbolAddress(&p_q,  g_q);  cudaGetSymbolAddress(&p_k,  g_k);
    cudaGetSymbolAddress(&p_wq, g_wq); cudaGetSymbolAddress(&p_wk, g_wk);

    // 1) split inputs into permuted hi/lo layouts
    split_qk_kernel<<<dim3(32, 64), dim3(32, 8)>>>(query, (float*)p_q);
    split_qk_kernel<<<dim3(32, 64), dim3(32, 8)>>>(key_t, (float*)p_k);
    split_w_kernel<<<4096, 256>>>(wq, (float*)p_wq);
    split_w_kernel<<<4096, 256>>>(wk, (float*)p_wk);

    // 2) projections
    proj_mma_kernel<<<dim3(8, 16, 2), 128, SMEM_BYTES>>>(bq, bk);

    // 3) score GEMMs
    score_mma_kernel<<<dim3(8, 8, 16), 128, SMEM_BYTES>>>();

    // 4) top-8 + softmax
    topk_kernel<<<NROWS / 8, 256>>>();

    // 5) gather + weighted sum
    out_kernel<<<dim3(NL, NV, NB), 256>>>(source, out);
}

// round 8
// speedup vs baseline: 1.2442x; 1.1588x over previous
#include <cuda_runtime.h>
#include <math.h>
#include <stdint.h>

#define NB    2
#define NL    1024
#define NV    8
#define NDVP  128
#define NDQ   1024
#define NDSRC 512
#define NW    4
#define NK    8
#define NROWS (NB * NV * NL)

// ---------------------------------------------------------------------------
// Device-global scratch (k-major operand layouts: [K][M])
// ---------------------------------------------------------------------------
__device__ float g_qh[1024 * 2048],  g_ql[1024 * 2048];   // query split  [k][b*l]
__device__ float g_kh[1024 * 2048],  g_kl[1024 * 2048];   // key_t split  [k][b*l]
__device__ float g_wqh[1024 * 1024], g_wql[1024 * 1024];  // wq split     [k][v*dvp]
__device__ float g_wkh[1024 * 1024], g_wkl[1024 * 1024];  // wk split     [k][v*dvp]
__device__ float g_pqh[1024 * 2048], g_pql[1024 * 2048];  // proj q split [v*dvp][b*l]
__device__ float g_pkh[1024 * 2048], g_pkl[1024 * 2048];  // proj k split [v*dvp][b*l]
__device__ float g_score[16 * 1024 * 1024];               // 64 MB [b,v,q,kq]
__device__ float g_wt[NROWS * NK];
__device__ int   g_ix[NROWS * NK];

// ---------------------------------------------------------------------------
// helpers
// ---------------------------------------------------------------------------
__device__ __forceinline__ float tf32_round(float x) {
    uint32_t u;
    asm("cvt.rna.tf32.f32 %0, %1;" : "=r"(u) : "f"(x));
    return __uint_as_float(u);
}
__device__ __forceinline__ uint32_t smem_u32(const void* p) {
    uint32_t a;
    asm("{ .reg .u64 t; cvta.to.shared.u64 t, %1; cvt.u32.u64 %0, t; }" : "=r"(a) : "l"(p));
    return a;
}
__device__ __forceinline__ void cp16(uint32_t dst, const void* src) {
    asm volatile("cp.async.cg.shared.global [%0], [%1], 16;" :: "r"(dst), "l"(src) : "memory");
}
__device__ __forceinline__ void cp_commit() { asm volatile("cp.async.commit_group;" ::: "memory"); }
__device__ __forceinline__ void cp_wait2()  { asm volatile("cp.async.wait_group 2;" ::: "memory"); }
__device__ __forceinline__ void cp_wait0()  { asm volatile("cp.async.wait_group 0;" ::: "memory"); }

__device__ __forceinline__ void mma_tf32(float* d, const uint32_t* a, const uint32_t* b) {
    asm volatile(
        "mma.sync.aligned.m16n8k8.row.col.f32.tf32.tf32.f32 "
        "{%0,%1,%2,%3}, {%4,%5,%6,%7}, {%8,%9}, {%0,%1,%2,%3};"
        : "+f"(d[0]), "+f"(d[1]), "+f"(d[2]), "+f"(d[3])
        : "r"(a[0]), "r"(a[1]), "r"(a[2]), "r"(a[3]), "r"(b[0]), "r"(b[1]));
}

// ---------------------------------------------------------------------------
// GEMM config: BM=128, BN=128, BK=16, 256 threads (8 warps, 4x2),
// warp tile 32x64, 3-stage cp.async pipeline. 2 CTAs/SM -> 16 warps/SM.
// Smem tiles are [BK][136] floats (stride 136 -> conflict-free fragments).
// ---------------------------------------------------------------------------
#define SA        136
#define TILE_F    (16 * SA)          // 2176 floats per tile
#define OFF_AH    0
#define OFF_AL    (1 * TILE_F)
#define OFF_BH    (2 * TILE_F)
#define OFF_BL    (3 * TILE_F)
#define STAGE_F   (4 * TILE_F)       // 8704 floats
#define NSTAGE    3
#define SMEM_BYTES (NSTAGE * STAGE_F * 4)  // 104448 bytes

__device__ __forceinline__ void load_tile(uint32_t sb, const float* src, int ld) {
    #pragma unroll
    for (int i = 0; i < 2; i++) {
        const int id = threadIdx.x + i * 256;       // 512 16B chunks per tile
        const int k = id >> 5, mc = id & 31;
        cp16(sb + (uint32_t)(k * SA + mc * 4) * 4, src + (size_t)k * ld + mc * 4);
    }
}

__device__ __forceinline__ void load_stage(uint32_t sb,
    const float* Ah, const float* Al, int lda,
    const float* Bh, const float* Bl, int ldb, int k0)
{
    load_tile(sb + OFF_AH * 4, Ah + (size_t)k0 * lda, lda);
    load_tile(sb + OFF_AL * 4, Al + (size_t)k0 * lda, lda);
    load_tile(sb + OFF_BH * 4, Bh + (size_t)k0 * ldb, ldb);
    load_tile(sb + OFF_BL * 4, Bl + (size_t)k0 * ldb, ldb);
    cp_commit();
}

__device__ __forceinline__ void compute_stage(const float* s, int warp_m, int warp_n,
                                              float acc[2][8][4])
{
    const int lane = threadIdx.x & 31;
    const int g = lane >> 2, tg = lane & 3;
    #pragma unroll
    for (int h = 0; h < 2; h++) {
        const int k8 = h * 8;
        const int r0 = (k8 + tg) * SA, r1 = (k8 + tg + 4) * SA;
        uint32_t aH[2][4], aL[2][4];
        #pragma unroll
        for (int ma = 0; ma < 2; ma++) {
            const int m = warp_m + ma * 16 + g;
            aH[ma][0] = __float_as_uint(s[OFF_AH + r0 + m]);
            aH[ma][1] = __float_as_uint(s[OFF_AH + r0 + m + 8]);
            aH[ma][2] = __float_as_uint(s[OFF_AH + r1 + m]);
            aH[ma][3] = __float_as_uint(s[OFF_AH + r1 + m + 8]);
            aL[ma][0] = __float_as_uint(s[OFF_AL + r0 + m]);
            aL[ma][1] = __float_as_uint(s[OFF_AL + r0 + m + 8]);
            aL[ma][2] = __float_as_uint(s[OFF_AL + r1 + m]);
            aL[ma][3] = __float_as_uint(s[OFF_AL + r1 + m + 8]);
        }
        #pragma unroll
        for (int nbh = 0; nbh < 2; nbh++) {
            uint32_t bH[4][2], bL[4][2];
            #pragma unroll
            for (int j = 0; j < 4; j++) {
                const int n = warp_n + (nbh * 4 + j) * 8 + g;
                bH[j][0] = __float_as_uint(s[OFF_BH + r0 + n]);
                bH[j][1] = __float_as_uint(s[OFF_BH + r1 + n]);
                bL[j][0] = __float_as_uint(s[OFF_BL + r0 + n]);
                bL[j][1] = __float_as_uint(s[OFF_BL + r1 + n]);
            }
            #pragma unroll
            for (int ma = 0; ma < 2; ma++)
                #pragma unroll
                for (int j = 0; j < 4; j++) {
                    float* d = acc[ma][nbh * 4 + j];
                    mma_tf32(d, aH[ma], bH[j]);
                    mma_tf32(d, aH[ma], bL[j]);
                    mma_tf32(d, aL[ma], bH[j]);
                }
        }
    }
}

__device__ __forceinline__ void gemm_mainloop(
    const float* Ah, const float* Al, int lda,
    const float* Bh, const float* Bl, int ldb,
    int nstages, float acc[2][8][4], float* smem)
{
    const uint32_t sb = smem_u32(smem);
    const int warp = threadIdx.x >> 5;
    const int warp_m = (warp & 3) * 32, warp_n = (warp >> 2) * 64;

    #pragma unroll
    for (int sp = 0; sp < NSTAGE; sp++)
        if (sp < nstages)
            load_stage(sb + sp * STAGE_F * 4, Ah, Al, lda, Bh, Bl, ldb, sp * 16);

    int buf = 0;
    for (int t = 0; t < nstages; ++t) {
        if (t + NSTAGE - 1 < nstages) cp_wait2(); else cp_wait0();
        __syncthreads();
        compute_stage(smem + buf * STAGE_F, warp_m, warp_n, acc);
        __syncthreads();
        if (t + NSTAGE < nstages)
            load_stage(sb + buf * STAGE_F * 4, Ah, Al, lda, Bh, Bl, ldb, (t + NSTAGE) * 16);
        buf = (buf == NSTAGE - 1) ? 0 : buf + 1;
    }
}

// ---------------------------------------------------------------------------
// Kernel 1a: split+transpose query & key -> k-major hi/lo. grid (32,64,2).
// ---------------------------------------------------------------------------
__global__ void __launch_bounds__(256) split_qk_kernel(
    const float* __restrict__ Q, const float* __restrict__ K)
{
    __shared__ float sh[32][33], sl[32][33];
    const float* X = blockIdx.z ? K : Q;
    float* Hi = blockIdx.z ? g_kh : g_qh;
    float* Lo = blockIdx.z ? g_kl : g_ql;
    const int tx = threadIdx.x, ty = threadIdx.y;
    const int c0 = blockIdx.x * 32, r0 = blockIdx.y * 32;
    #pragma unroll
    for (int j = 0; j < 4; j++) {
        const int r = r0 + ty + j * 8;
        const float v = X[(size_t)r * 1024 + c0 + tx];
        const float h = tf32_round(v);
        sh[ty + j * 8][tx] = h;
        sl[ty + j * 8][tx] = tf32_round(v - h);
    }
    __syncthreads();
    #pragma unroll
    for (int j = 0; j < 4; j++) {
        const int c = c0 + ty + j * 8;
        Hi[(size_t)c * 2048 + r0 + tx] = sh[tx][ty + j * 8];
        Lo[(size_t)c * 2048 + r0 + tx] = sl[tx][ty + j * 8];
    }
}

// ---------------------------------------------------------------------------
// Kernel 1b: split+transpose wq & wk -> k-major hi/lo. grid (32,32,2).
// ---------------------------------------------------------------------------
__global__ void __launch_bounds__(256) split_w_kernel(
    const float* __restrict__ WQ, const float* __restrict__ WK)
{
    __shared__ float sh[32][33], sl[32][33];
    const float* X = blockIdx.z ? WK : WQ;
    float* Hi = blockIdx.z ? g_wkh : g_wqh;
    float* Lo = blockIdx.z ? g_wkl : g_wql;
    const int tx = threadIdx.x, ty = threadIdx.y;
    const int c0 = blockIdx.x * 32, r0 = blockIdx.y * 32;
    #pragma unroll
    for (int j = 0; j < 4; j++) {
        const int r = r0 + ty + j * 8;
        const float v = X[(size_t)r * 1024 + c0 + tx];
        const float h = tf32_round(v);
        sh[ty + j * 8][tx] = h;
        sl[ty + j * 8][tx] = tf32_round(v - h);
    }
    __syncthreads();
    #pragma unroll
    for (int j = 0; j < 4; j++) {
        const int c = c0 + ty + j * 8;
        Hi[(size_t)c * 1024 + r0 + tx] = sh[tx][ty + j * 8];
        Lo[(size_t)c * 1024 + r0 + tx] = sl[tx][ty + j * 8];
    }
}

// ---------------------------------------------------------------------------
// Kernel 2: projections. z=0 -> q, z=1 -> k. grid (8, 16, 2), 256 thr.
// Epilogue: +bias, tf32 split, TRANSPOSED store ([col][row]) for score GEMM.
// ---------------------------------------------------------------------------
__global__ void __launch_bounds__(256, 2) proj_mma_kernel(
    const float* __restrict__ bq, const float* __restrict__ bk)
{
    extern __shared__ float smem[];
    const int z = blockIdx.z;
    const int m0 = blockIdx.y * 128, n0 = blockIdx.x * 128;

    const float* Ah = (z ? g_kh : g_qh) + m0;     // [1024][2048]
    const float* Al = (z ? g_kl : g_ql) + m0;
    const float* Bh = (z ? g_wkh : g_wqh) + n0;   // [1024][1024]
    const float* Bl = (z ? g_wkl : g_wql) + n0;

    float acc[2][8][4];
    #pragma unroll
    for (int i = 0; i < 2; i++)
        #pragma unroll
        for (int j = 0; j < 8; j++)
            #pragma unroll
            for (int r = 0; r < 4; r++) acc[i][j][r] = 0.f;

    gemm_mainloop(Ah, Al, 2048, Bh, Bl, 1024, NDQ / 16, acc, smem);

    const float* bias = z ? bk : bq;
    float* Ho = z ? g_pkh : g_pqh;
    float* Lo_ = z ? g_pkl : g_pql;

    const int warp = threadIdx.x >> 5, lane = threadIdx.x & 31;
    const int warp_m = (warp & 3) * 32, warp_n = (warp >> 2) * 64;
    const int g = lane >> 2, tg = lane & 3;

    #pragma unroll
    for (int ma = 0; ma < 2; ma++)
        #pragma unroll
        for (int nb = 0; nb < 8; nb++) {
            const int row = m0 + warp_m + ma * 16 + g;
            const int col = n0 + warp_n + nb * 8 + 2 * tg;
            #pragma unroll
            for (int rr = 0; rr < 4; rr++) {
                const int r = row + (rr >> 1) * 8;
                const int c = col + (rr & 1);
                const float v = acc[ma][nb][rr] + __ldg(&bias[c]);
                const float h = tf32_round(v);
                Ho[(size_t)c * 2048 + r]  = h;
                Lo_[(size_t)c * 2048 + r] = tf32_round(v - h);
            }
        }
}

// ---------------------------------------------------------------------------
// Kernel 3: score[b,v] = q_v * k_v^T (K=128). grid (8, 8, 16), 256 thr.
// ---------------------------------------------------------------------------
__global__ void __launch_bounds__(256, 2) score_mma_kernel()
{
    extern __shared__ float smem[];
    const int z = blockIdx.z;
    const int b = z >> 3, v = z & 7;
    const int m0 = blockIdx.y * 128, n0 = blockIdx.x * 128;

    const size_t base = (size_t)(v * 128) * 2048 + b * 1024;
    const float* Ah = g_pqh + base + m0;
    const float* Al = g_pql + base + m0;
    const float* Bh = g_pkh + base + n0;
    const float* Bl = g_pkl + base + n0;

    float acc[2][8][4];
    #pragma unroll
    for (int i = 0; i < 2; i++)
        #pragma unroll
        for (int j = 0; j < 8; j++)
            #pragma unroll
            for (int r = 0; r < 4; r++) acc[i][j][r] = 0.f;

    gemm_mainloop(Ah, Al, 2048, Bh, Bl, 2048, NDVP / 16, acc, smem);

    float* C = g_score + ((size_t)z << 20);
    const int warp = threadIdx.x >> 5, lane = threadIdx.x & 31;
    const int warp_m = (warp & 3) * 32, warp_n = (warp >> 2) * 64;
    const int g = lane >> 2, tg = lane & 3;

    #pragma unroll
    for (int ma = 0; ma < 2; ma++)
        #pragma unroll
        for (int nb = 0; nb < 8; nb++) {
            const int row = m0 + warp_m + ma * 16 + g;
            const int col = n0 + warp_n + nb * 8 + 2 * tg;
            *(float2*)&C[(size_t)row * 1024 + col] =
                make_float2(acc[ma][nb][0], acc[ma][nb][1]);
            *(float2*)&C[(size_t)(row + 8) * 1024 + col] =
                make_float2(acc[ma][nb][2], acc[ma][nb][3]);
        }
}

// ---------------------------------------------------------------------------
// Kernel 4: top-8 + softmax per score row. One warp per row.
// ---------------------------------------------------------------------------
__global__ void __launch_bounds__(256) topk_kernel()
{
    const int rid  = blockIdx.x * 8 + (threadIdx.x >> 5);
    const int lane = threadIdx.x & 31;
    const float* row = g_score + (size_t)rid * NL;

    float best[NK];
    int   bidx[NK];
    #pragma unroll
    for (int j = 0; j < NK; j++) { best[j] = -INFINITY; bidx[j] = 0x7fffffff; }

    #pragma unroll 4
    for (int i = 0; i < 32; i++) {
        const int idx = i * 32 + lane;
        const float val = row[idx];
        if (val > best[NK - 1]) {
            best[NK - 1] = val; bidx[NK - 1] = idx;
            #pragma unroll
            for (int j = NK - 1; j > 0; --j) {
                if (best[j] > best[j - 1]) {
                    float tv = best[j]; best[j] = best[j - 1]; best[j - 1] = tv;
                    int   ti = bidx[j]; bidx[j] = bidx[j - 1]; bidx[j - 1] = ti;
                }
            }
        }
    }

    float vals[NK]; int inds[NK];
    #pragma unroll
    for (int r = 0; r < NK; r++) {
        float v0 = best[0]; int i0 = bidx[0];
        #pragma unroll
        for (int off = 16; off > 0; off >>= 1) {
            float ov = __shfl_down_sync(0xffffffffu, v0, off);
            int   oi = __shfl_down_sync(0xffffffffu, i0, off);
            if (ov > v0 || (ov == v0 && oi < i0)) { v0 = ov; i0 = oi; }
        }
        v0 = __shfl_sync(0xffffffffu, v0, 0);
        i0 = __shfl_sync(0xffffffffu, i0, 0);
        vals[r] = v0; inds[r] = i0;
        if (lane == (i0 & 31)) {
            #pragma unroll
            for (int j = 0; j < NK - 1; j++) { best[j] = best[j + 1]; bidx[j] = bidx[j + 1]; }
            best[NK - 1] = -INFINITY; bidx[NK - 1] = 0x7fffffff;
        }
    }

    if (lane == 0) {
        const float m = vals[0];
        float e[NK], sum = 0.f;
        #pragma unroll
        for (int r = 0; r < NK; r++) { e[r] = expf(vals[r] - m); sum += e[r]; }
        const float inv = 1.f / sum;
        #pragma unroll
        for (int r = 0; r < NK; r++) {
            g_wt[rid * NK + r] = e[r] * inv;
            g_ix[rid * NK + r] = inds[r];
        }
    }
}

// ---------------------------------------------------------------------------
// Kernel 5: windowed gather + weighted sum. grid (1024, 8, 2), 256 threads.
// ---------------------------------------------------------------------------
__global__ void __launch_bounds__(256) out_kernel(
    const float* __restrict__ source, float* __restrict__ out)
{
    const int q = blockIdx.x, v = blockIdx.y, b = blockIdx.z;
    const int tid = threadIdx.x;
    const int rid = (b * NV + v) * NL + q;

    float wloc[NK]; int iloc[NK];
    #pragma unroll
    for (int r = 0; r < NK; r++) {
        wloc[r] = __ldg(&g_wt[rid * NK + r]);
        iloc[r] = __ldg(&g_ix[rid * NK + r]);
    }

    const float4* src4 = (const float4*)(source + b * (NL * NDSRC));
    float4* out4 = (float4*)out + (size_t)rid * (NW * NDSRC / 4);

    #pragma unroll
    for (int e2 = 0; e2 < 2; e2++) {
        const int id = tid + e2 * 256;
        const int w = id >> 7;
        const int f = id & 127;
        float4 acc = make_float4(0.f, 0.f, 0.f, 0.f);
        #pragma unroll
        for (int r = 0; r < NK; r++) {
            const int rr = iloc[r] + w - 1;
            if ((unsigned)rr < (unsigned)NL) {
                const float4 s = __ldg(&src4[rr * (NDSRC / 4) + f]);
                const float wt = wloc[r];
                acc.x += wt * s.x; acc.y += wt * s.y;
                acc.z += wt * s.z; acc.w += wt * s.w;
            }
        }
        out4[id] = acc;
    }
}

// ---------------------------------------------------------------------------
extern "C" void kernel_launch(void* const* d_in, const int* in_sizes, int n_in,
                              void* d_out, int out_size)
{
    const float* query  = (const float*)d_in[0];
    const float* key_t  = (const float*)d_in[1];
    const float* source = (const float*)d_in[2];
    const float* wq     = (const float*)d_in[3];
    const float* bq     = (const float*)d_in[4];
    const float* wk     = (const float*)d_in[5];
    const float* bk     = (const float*)d_in[6];
    float* out = (float*)d_out;

    static int inited = 0;
    if (!inited) {
        cudaFuncSetAttribute(proj_mma_kernel,  cudaFuncAttributeMaxDynamicSharedMemorySize, SMEM_BYTES);
        cudaFuncSetAttribute(score_mma_kernel, cudaFuncAttributeMaxDynamicSharedMemorySize, SMEM_BYTES);
        inited = 1;
    }

    // 1) split inputs into tf32 hi/lo, transposed to k-major (batched)
    split_qk_kernel<<<dim3(32, 64, 2), dim3(32, 8)>>>(query, key_t);
    split_w_kernel<<<dim3(32, 32, 2), dim3(32, 8)>>>(wq, wk);

    // 2) projections (tensor pipe via mma.sync tf32), epilogue re-splits
    proj_mma_kernel<<<dim3(8, 16, 2), 256, SMEM_BYTES>>>(bq, bk);

    // 3) score GEMMs
    score_mma_kernel<<<dim3(8, 8, 16), 256, SMEM_BYTES>>>();

    // 4) top-8 + softmax
    topk_kernel<<<NROWS / 8, 256>>>();

    // 5) gather + weighted sum
    out_kernel<<<dim3(NL, NV, NB), 256>>>(source, out);
}